// round 3
// baseline (speedup 1.0000x reference)
#include <cuda_runtime.h>
#include <math.h>

#define Bs   16
#define Cc   256
#define Hh   128
#define Ww   128
#define HW   16384
#define CHUNK 2          // batches per L2-blocked chunk (32MB scratch -> L2-resident)
#define PIX  32          // pixels per scatter block
#define SS   258         // smem row stride (words): even -> 8B-aligned LDS.64
#define EPSV 1e-05f

// Reused scratch: transposed accumulator [CHUNK][HW][C] (32 MB, stays hot in L2
// because the same addresses are reused every chunk), plus attention norm.
// Zero-initialized at module load; k_div reads-and-zeroes, so every graph
// replay starts from zeroed scratch (deterministic).
__device__ float g_feat[(size_t)CHUNK * HW * Cc];
__device__ float g_att[CHUNK * HW];    // zero-based; EPS added in k_div

// -------------------------------------------- fused conv + scatter
// Block = 32 consecutive pixels x all 256 channels.
//  * coalesced LDG of the x tile into SMEM (transposing to [pixel][channel])
//  * per-pixel 3-way dot over C (warp partials + smem tree reduce)
//  * offset output write, attention-norm scalar atomic
//  * per-pixel 256-channel scatter as 2 rounds of red.global.add.v4.f32
//    into the contiguous 1KB row g_feat[b][idx][:]
__global__ __launch_bounds__(256) void k_scatter(
    const float* __restrict__ x, const float* __restrict__ cw,
    const float* __restrict__ cb, float* __restrict__ offo, int b0) {
    __shared__ float s_x[PIX * SS];     // 33 KB tile, [pixel][channel]
    __shared__ float s_w[3 * Cc];
    __shared__ float s_red[3 * 8 * 32];
    __shared__ float s_att[PIX];
    __shared__ int   s_idx[PIX];

    const int tid  = threadIdx.x;
    const int lane = tid & 31;
    const int warp = tid >> 5;
    const int bl   = blockIdx.y;        // local batch (scratch index)
    const int b    = b0 + bl;           // global batch
    const int hw0  = blockIdx.x * PIX;

    for (int i = tid; i < 3 * Cc; i += 256) s_w[i] = cw[i];
    __syncthreads();

    const float* xb = x + (size_t)b * Cc * HW + hw0;
    float a0 = 0.f, a1 = 0.f, a2 = 0.f;
#pragma unroll
    for (int k = 0; k < Cc / 8; k++) {
        int c = k * 8 + warp;                        // warp owns channel slice
        float v = __ldg(xb + (size_t)c * HW + lane); // coalesced over 32 pixels
        s_x[lane * SS + c] = v;
        a0 = fmaf(v, s_w[c],          a0);
        a1 = fmaf(v, s_w[Cc + c],     a1);
        a2 = fmaf(v, s_w[2 * Cc + c], a2);
    }
    s_red[(0 * 8 + warp) * 32 + lane] = a0;
    s_red[(1 * 8 + warp) * 32 + lane] = a1;
    s_red[(2 * 8 + warp) * 32 + lane] = a2;
    __syncthreads();

    if (warp == 0) {                    // lane == pixel within tile
        float r0 = cb[0], r1 = cb[1], r2 = cb[2];
#pragma unroll
        for (int w = 0; w < 8; w++) {
            r0 += s_red[w * 32 + lane];
            r1 += s_red[(8 + w) * 32 + lane];
            r2 += s_red[(16 + w) * 32 + lane];
        }
        float offy = r0 * (float)Hh;
        float offx = r1 * (float)Ww;
        float att  = expf(r2);
        int hw = hw0 + lane;
        int hh = hw >> 7, wc = hw & 127;
        // round-half-even (rintf) then clip, matching jnp.round + clip
        int iy = (int)fminf(fmaxf(rintf((float)hh + offy), 0.f), 127.f);
        int ix = (int)fminf(fmaxf(rintf((float)wc + offx), 0.f), 127.f);
        int idx = (iy << 7) + ix;
        s_att[lane] = att;
        s_idx[lane] = idx;
        size_t ob = (size_t)b * 2 * HW + hw;       // offset: [B][2][H][W]
        offo[ob]      = offy;
        offo[ob + HW] = offx;
        atomicAdd(&g_att[bl * HW + idx], att);
    }
    __syncthreads();

    // Scatter: each warp handles 4 pixels; per pixel, 2 x red.v4 per lane
    // covering channels [4*lane + 128*r .. +3] -> contiguous 1KB destination.
#pragma unroll
    for (int p = warp; p < PIX; p += 8) {
        float att = s_att[p];
        float* dst = g_feat + ((size_t)bl * HW + s_idx[p]) * Cc;
        const float* src = s_x + p * SS;
#pragma unroll
        for (int r = 0; r < 2; r++) {
            int c0 = r * 128 + 4 * lane;
            float2 u = *reinterpret_cast<const float2*>(src + c0);
            float2 v = *reinterpret_cast<const float2*>(src + c0 + 2);
            asm volatile(
                "red.global.add.v4.f32 [%0], {%1, %2, %3, %4};" ::
                "l"(dst + c0),
                "f"(u.x * att), "f"(u.y * att), "f"(v.x * att), "f"(v.y * att)
                : "memory");
        }
    }
}

// ---- normalize + transpose to [B][C][HW], read-and-zero scratch in one pass
// One block owns [bl][hw0..hw0+31][all 256 channels] (a contiguous 32 KB
// region of g_feat) plus the 32 g_att entries — unique ownership makes the
// read-and-zero race-free within the launch.
__global__ __launch_bounds__(256) void k_div(float* __restrict__ out, int b0) {
    __shared__ float t[32][33];
    __shared__ float inv[32];
    const int tx = threadIdx.x;         // 32
    const int ty = threadIdx.y;         // 8
    const int bl = blockIdx.y;
    const int b  = b0 + bl;
    const int hw0 = blockIdx.x * 32;

    if (ty == 0) {
        float a = g_att[bl * HW + hw0 + tx];
        g_att[bl * HW + hw0 + tx] = 0.f;          // re-zero for next chunk
        inv[tx] = 1.0f / (a + EPSV);
    }
    __syncthreads();

#pragma unroll
    for (int cg = 0; cg < 8; cg++) {
        const int c0 = cg * 32;
#pragma unroll
        for (int j = ty; j < 32; j += 8) {
            float* p = g_feat + ((size_t)bl * HW + hw0 + j) * Cc + c0 + tx;
            float v = *p;
            *p = 0.f;                             // fused re-zero (same addr, same thread)
            t[j][tx] = v;
        }
        __syncthreads();
#pragma unroll
        for (int j = ty; j < 32; j += 8)
            out[((size_t)b * Cc + c0 + j) * HW + hw0 + tx] = t[tx][j] * inv[tx];
        __syncthreads();
    }
}

// ---------------------------------------------------------------- launch
extern "C" void kernel_launch(void* const* d_in, const int* in_sizes, int n_in,
                              void* d_out, int out_size) {
    const float* x  = (const float*)d_in[0];   // [16,256,128,128]
    const float* cw = (const float*)d_in[1];   // [3,256]
    const float* cb = (const float*)d_in[2];   // [3]
    float* out  = (float*)d_out;                        // [B,C,HW]
    float* offo = out + (size_t)Bs * Cc * HW;           // [B,2,H,W]

    for (int b0 = 0; b0 < Bs; b0 += CHUNK) {
        k_scatter<<<dim3(HW / PIX, CHUNK), 256>>>(x, cw, cb, offo, b0);
        k_div<<<dim3(HW / 32, CHUNK), dim3(32, 8)>>>(out, b0);
    }
}

// round 4
// speedup vs baseline: 6.2439x; 6.2439x over previous
#include <cuda_runtime.h>
#include <math.h>

#define Bs   16
#define Cc   256
#define Hh   128
#define Ww   128
#define HW   16384
#define CHUNK 2          // batches per L2-blocked chunk (32MB scratch -> L2-resident)
#define PIX  32          // pixels per scatter block
#define SS   258         // smem row stride (words): even -> 8B-aligned LDS.64
#define EPSV 1e-05f

// Reused scratch: transposed accumulator [CHUNK][HW][C] (32 MB, stays hot in L2
// because the same addresses are reused every chunk), plus attention norm.
// Zero-initialized at module load; k_div re-zeros in a separate pass AFTER the
// transpose reads complete (never store to a line with a pending load miss —
// that was R3's 16x pathology), so every graph replay starts zeroed.
__device__ float g_feat[(size_t)CHUNK * HW * Cc];
__device__ float g_att[CHUNK * HW];    // zero-based; EPS added in k_div

// -------------------------------------------- fused conv + scatter
// Block = 32 consecutive pixels x all 256 channels.
//  * coalesced LDG of the x tile into SMEM (transposing to [pixel][channel])
//  * per-pixel 3-way dot over C (warp partials + smem tree reduce)
//  * offset output write, attention-norm scalar atomic
//  * per-pixel 256-channel scatter as 2 rounds of red.global.add.v4.f32
//    into the contiguous 1KB row g_feat[b][idx][:]
__global__ __launch_bounds__(256) void k_scatter(
    const float* __restrict__ x, const float* __restrict__ cw,
    const float* __restrict__ cb, float* __restrict__ offo, int b0) {
    __shared__ float s_x[PIX * SS];     // 33 KB tile, [pixel][channel]
    __shared__ float s_w[3 * Cc];
    __shared__ float s_red[3 * 8 * 32];
    __shared__ float s_att[PIX];
    __shared__ int   s_idx[PIX];

    const int tid  = threadIdx.x;
    const int lane = tid & 31;
    const int warp = tid >> 5;
    const int bl   = blockIdx.y;        // local batch (scratch index)
    const int b    = b0 + bl;           // global batch
    const int hw0  = blockIdx.x * PIX;

    for (int i = tid; i < 3 * Cc; i += 256) s_w[i] = cw[i];
    __syncthreads();

    const float* xb = x + (size_t)b * Cc * HW + hw0;
    float a0 = 0.f, a1 = 0.f, a2 = 0.f;
#pragma unroll
    for (int k = 0; k < Cc / 8; k++) {
        int c = k * 8 + warp;                        // warp owns channel slice
        float v = __ldg(xb + (size_t)c * HW + lane); // coalesced over 32 pixels
        s_x[lane * SS + c] = v;
        a0 = fmaf(v, s_w[c],          a0);
        a1 = fmaf(v, s_w[Cc + c],     a1);
        a2 = fmaf(v, s_w[2 * Cc + c], a2);
    }
    s_red[(0 * 8 + warp) * 32 + lane] = a0;
    s_red[(1 * 8 + warp) * 32 + lane] = a1;
    s_red[(2 * 8 + warp) * 32 + lane] = a2;
    __syncthreads();

    if (warp == 0) {                    // lane == pixel within tile
        float r0 = cb[0], r1 = cb[1], r2 = cb[2];
#pragma unroll
        for (int w = 0; w < 8; w++) {
            r0 += s_red[w * 32 + lane];
            r1 += s_red[(8 + w) * 32 + lane];
            r2 += s_red[(16 + w) * 32 + lane];
        }
        float offy = r0 * (float)Hh;
        float offx = r1 * (float)Ww;
        float att  = expf(r2);
        int hw = hw0 + lane;
        int hh = hw >> 7, wc = hw & 127;
        // round-half-even (rintf) then clip, matching jnp.round + clip
        int iy = (int)fminf(fmaxf(rintf((float)hh + offy), 0.f), 127.f);
        int ix = (int)fminf(fmaxf(rintf((float)wc + offx), 0.f), 127.f);
        int idx = (iy << 7) + ix;
        s_att[lane] = att;
        s_idx[lane] = idx;
        size_t ob = (size_t)b * 2 * HW + hw;       // offset: [B][2][H][W]
        offo[ob]      = offy;
        offo[ob + HW] = offx;
        atomicAdd(&g_att[bl * HW + idx], att);
    }
    __syncthreads();

    // Scatter: each warp handles 4 pixels; per pixel, 2 x red.v4 per lane
    // covering channels [4*lane + 128*r .. +3] -> contiguous 1KB destination.
#pragma unroll
    for (int p = warp; p < PIX; p += 8) {
        float att = s_att[p];
        float* dst = g_feat + ((size_t)bl * HW + s_idx[p]) * Cc;
        const float* src = s_x + p * SS;
#pragma unroll
        for (int r = 0; r < 2; r++) {
            int c0 = r * 128 + 4 * lane;
            float2 u = *reinterpret_cast<const float2*>(src + c0);
            float2 v = *reinterpret_cast<const float2*>(src + c0 + 2);
            asm volatile(
                "red.global.add.v4.f32 [%0], {%1, %2, %3, %4};" ::
                "l"(dst + c0),
                "f"(u.x * att), "f"(u.y * att), "f"(v.x * att), "f"(v.y * att)
                : "memory");
        }
    }
}

// ----------------- normalize + transpose to [B][C][HW] + re-zero scratch
// One block owns [bl][hw0..hw0+31][all 256 channels] (a contiguous 32 KB
// region of g_feat) plus the 32 g_att entries — unique ownership makes the
// post-consume re-zero race-free within the launch. The zero pass runs AFTER
// all loads of the region have completed (separate pass, R2-proven).
__global__ __launch_bounds__(256) void k_div(float* __restrict__ out, int b0) {
    __shared__ float t[32][33];
    __shared__ float inv[32];
    const int tx = threadIdx.x;         // 32
    const int ty = threadIdx.y;         // 8
    const int tid = ty * 32 + tx;
    const int bl = blockIdx.y;
    const int b  = b0 + bl;
    const int hw0 = blockIdx.x * 32;

    if (ty == 0)
        inv[tx] = 1.0f / (g_att[bl * HW + hw0 + tx] + EPSV);
    __syncthreads();

#pragma unroll
    for (int cg = 0; cg < 8; cg++) {
        const int c0 = cg * 32;
#pragma unroll
        for (int j = ty; j < 32; j += 8)
            t[j][tx] = g_feat[((size_t)bl * HW + hw0 + j) * Cc + c0 + tx];
        __syncthreads();
#pragma unroll
        for (int j = ty; j < 32; j += 8)
            out[((size_t)b * Cc + c0 + j) * HW + hw0 + tx] = t[tx][j] * inv[tx];
        __syncthreads();
    }

    // Re-zero this block's scratch region (loads above have all completed).
    float4* fz = reinterpret_cast<float4*>(g_feat + ((size_t)bl * HW + hw0) * Cc);
    float4 z = make_float4(0.f, 0.f, 0.f, 0.f);
#pragma unroll
    for (int i = tid; i < 32 * Cc / 4; i += 256)
        fz[i] = z;
    if (tid < 32)
        g_att[bl * HW + hw0 + tid] = 0.f;
}

// ---------------------------------------------------------------- launch
extern "C" void kernel_launch(void* const* d_in, const int* in_sizes, int n_in,
                              void* d_out, int out_size) {
    const float* x  = (const float*)d_in[0];   // [16,256,128,128]
    const float* cw = (const float*)d_in[1];   // [3,256]
    const float* cb = (const float*)d_in[2];   // [3]
    float* out  = (float*)d_out;                        // [B,C,HW]
    float* offo = out + (size_t)Bs * Cc * HW;           // [B,2,H,W]

    for (int b0 = 0; b0 < Bs; b0 += CHUNK) {
        k_scatter<<<dim3(HW / PIX, CHUNK), 256>>>(x, cw, cb, offo, b0);
        k_div<<<dim3(HW / 32, CHUNK), dim3(32, 8)>>>(out, b0);
    }
}

// round 5
// speedup vs baseline: 7.1944x; 1.1522x over previous
#include <cuda_runtime.h>
#include <math.h>

#define Bs   16
#define Cc   256
#define Hh   128
#define Ww   128
#define HW   16384
#define CHUNK 2          // batches per L2-blocked chunk (32MB scratch -> L2-resident)
#define PIX  32          // pixels per scatter block
#define SS   258         // smem row stride (words): even -> 8B-aligned LDS.64
#define EPSV 1e-05f
#define TSTRIDE 1064     // words per transpose tile (32*33 + 8 pad)

// Reused scratch: transposed accumulator [CHUNK][HW][C] (32 MB, L2-resident),
// plus attention norm. Zero-initialized at module load; k_div re-zeros in a
// separate pass AFTER the transpose reads complete (R3 lesson: never store to
// a line with a pending same-thread load miss), so replays start zeroed.
__device__ float g_feat[(size_t)CHUNK * HW * Cc];
__device__ float g_att[CHUNK * HW];    // zero-based; EPS added in k_div

// -------------------------------------------- fused conv + scatter
__global__ __launch_bounds__(256) void k_scatter(
    const float* __restrict__ x, const float* __restrict__ cw,
    const float* __restrict__ cb, float* __restrict__ offo, int b0) {
    __shared__ float s_x[PIX * SS];     // 33 KB tile, [pixel][channel]
    __shared__ float s_w[3 * Cc];
    __shared__ float s_red[3 * 8 * 32];
    __shared__ float s_att[PIX];
    __shared__ int   s_idx[PIX];

    const int tid  = threadIdx.x;
    const int lane = tid & 31;
    const int warp = tid >> 5;
    const int bl   = blockIdx.y;        // local batch (scratch index)
    const int b    = b0 + bl;           // global batch
    const int hw0  = blockIdx.x * PIX;

    for (int i = tid; i < 3 * Cc; i += 256) s_w[i] = cw[i];
    __syncthreads();

    const float* xb = x + (size_t)b * Cc * HW + hw0;
    float a0 = 0.f, a1 = 0.f, a2 = 0.f;
#pragma unroll
    for (int k = 0; k < Cc / 8; k++) {
        int c = k * 8 + warp;                        // warp owns channel slice
        float v = __ldg(xb + (size_t)c * HW + lane); // coalesced over 32 pixels
        s_x[lane * SS + c] = v;
        a0 = fmaf(v, s_w[c],          a0);
        a1 = fmaf(v, s_w[Cc + c],     a1);
        a2 = fmaf(v, s_w[2 * Cc + c], a2);
    }
    s_red[(0 * 8 + warp) * 32 + lane] = a0;
    s_red[(1 * 8 + warp) * 32 + lane] = a1;
    s_red[(2 * 8 + warp) * 32 + lane] = a2;
    __syncthreads();

    if (warp == 0) {                    // lane == pixel within tile
        float r0 = cb[0], r1 = cb[1], r2 = cb[2];
#pragma unroll
        for (int w = 0; w < 8; w++) {
            r0 += s_red[w * 32 + lane];
            r1 += s_red[(8 + w) * 32 + lane];
            r2 += s_red[(16 + w) * 32 + lane];
        }
        float offy = r0 * (float)Hh;
        float offx = r1 * (float)Ww;
        float att  = expf(r2);
        int hw = hw0 + lane;
        int hh = hw >> 7, wc = hw & 127;
        // round-half-even (rintf) then clip, matching jnp.round + clip
        int iy = (int)fminf(fmaxf(rintf((float)hh + offy), 0.f), 127.f);
        int ix = (int)fminf(fmaxf(rintf((float)wc + offx), 0.f), 127.f);
        int idx = (iy << 7) + ix;
        s_att[lane] = att;
        s_idx[lane] = idx;
        size_t ob = (size_t)b * 2 * HW + hw;       // offset: [B][2][H][W]
        offo[ob]      = offy;
        offo[ob + HW] = offx;
        atomicAdd(&g_att[bl * HW + idx], att);
    }
    __syncthreads();

    // Scatter: each warp handles 4 pixels; per pixel, 2 x red.v4 per lane
    // covering a contiguous 1KB destination row g_feat[bl][idx][:].
#pragma unroll
    for (int p = warp; p < PIX; p += 8) {
        float att = s_att[p];
        float* dst = g_feat + ((size_t)bl * HW + s_idx[p]) * Cc;
        const float* src = s_x + p * SS;
#pragma unroll
        for (int r = 0; r < 2; r++) {
            int c0 = r * 128 + 4 * lane;
            float2 u = *reinterpret_cast<const float2*>(src + c0);
            float2 v = *reinterpret_cast<const float2*>(src + c0 + 2);
            asm volatile(
                "red.global.add.v4.f32 [%0], {%1, %2, %3, %4};" ::
                "l"(dst + c0),
                "f"(u.x * att), "f"(u.y * att), "f"(v.x * att), "f"(v.y * att)
                : "memory");
        }
    }
}

// ----------------- normalize + transpose to [B][C][HW] + re-zero scratch
// One block owns [bl][hw0..hw0+31][all 256 channels] (contiguous 32 KB of
// g_feat) + 32 g_att entries. Single-barrier structure:
//   * 8 independent LDG.128 per thread (MLP=8) into 8 padded 32x33 smem tiles
//   * one __syncthreads
//   * conflict-free stride-33 LDS + coalesced STG of out
//   * separate float4 zero pass (loads already consumed -> no pending-miss)
__global__ __launch_bounds__(256) void k_div(float* __restrict__ out, int b0) {
    __shared__ float t[8 * TSTRIDE];    // ~34 KB
    __shared__ float inv[32];
    const int tid = threadIdx.x;
    const int bl  = blockIdx.y;
    const int b   = b0 + bl;
    const int hw0 = blockIdx.x * 32;

    if (tid < 32)
        inv[tid] = 1.0f / (g_att[bl * HW + hw0 + tid] + EPSV);

    const float4* src = reinterpret_cast<const float4*>(
        g_feat + ((size_t)bl * HW + hw0) * Cc);
#pragma unroll
    for (int k = 0; k < 8; k++) {
        int i  = tid + k * 256;         // [0, 2048)
        int hw = i >> 6;                // 0..31 (pixel)
        int cq = i & 63;                // float4 index within 256 channels
        float4 v = src[i];
        int g  = cq >> 3;               // channel group (tile)
        int cc = (cq & 7) * 4;          // channel within tile
        float* d = &t[g * TSTRIDE + hw * 33 + cc];
        d[0] = v.x; d[1] = v.y; d[2] = v.z; d[3] = v.w;
    }
    __syncthreads();

    const int tx = tid & 31;            // hw within tile
    const int ty = tid >> 5;            // warp -> channel row stepper
#pragma unroll
    for (int g = 0; g < 8; g++) {
#pragma unroll
        for (int j = ty; j < 32; j += 8)
            out[((size_t)b * Cc + g * 32 + j) * HW + hw0 + tx] =
                t[g * TSTRIDE + tx * 33 + j] * inv[tx];
    }

    // Re-zero this block's scratch region (all loads above completed).
    float4* fz = reinterpret_cast<float4*>(g_feat + ((size_t)bl * HW + hw0) * Cc);
    float4 z = make_float4(0.f, 0.f, 0.f, 0.f);
#pragma unroll
    for (int k = 0; k < 8; k++)
        fz[tid + k * 256] = z;
    if (tid < 32)
        g_att[bl * HW + hw0 + tid] = 0.f;
}

// ---------------------------------------------------------------- launch
extern "C" void kernel_launch(void* const* d_in, const int* in_sizes, int n_in,
                              void* d_out, int out_size) {
    const float* x  = (const float*)d_in[0];   // [16,256,128,128]
    const float* cw = (const float*)d_in[1];   // [3,256]
    const float* cb = (const float*)d_in[2];   // [3]
    float* out  = (float*)d_out;                        // [B,C,HW]
    float* offo = out + (size_t)Bs * Cc * HW;           // [B,2,H,W]

    for (int b0 = 0; b0 < Bs; b0 += CHUNK) {
        k_scatter<<<dim3(HW / PIX, CHUNK), 256>>>(x, cw, cb, offo, b0);
        k_div<<<dim3(HW / 32, CHUNK), 256>>>(out, b0);
    }
}